// round 1
// baseline (speedup 1.0000x reference)
#include <cuda_runtime.h>
#include <cstdint>

#define NN 100000
#define EE 1600000
#define HH 128
#define GG 512
#define BN_EPS 1e-5f
#define SCAN_B 1024
#define NB ((NN + SCAN_B - 1) / SCAN_B)   // 98 scan blocks

// ---------------- scratch (device globals: no allocation allowed) -----------
__device__ float g_buf0[(size_t)NN * HH];   // GEMM output t = X @ W
__device__ float g_buf1[(size_t)NN * HH];   // aggregated/activated h
__device__ float g_dinv[NN];
__device__ int   g_deg[NN];
__device__ int   g_rowptr[NN + 1];
__device__ int   g_cursor[NN];
__device__ int   g_col[EE];
__device__ float g_gsum[GG];
__device__ int   g_gcnt[GG];
__device__ int   g_part[NB];

// ---------------- preprocessing kernels ------------------------------------
__global__ void k_zero() {
    int i = blockIdx.x * blockDim.x + threadIdx.x;
    if (i < NN) g_deg[i] = 0;
    if (i < GG) { g_gsum[i] = 0.0f; g_gcnt[i] = 0; }
}

__global__ void k_hist(const int* __restrict__ ei) {
    int e = blockIdx.x * blockDim.x + threadIdx.x;
    if (e < EE) atomicAdd(&g_deg[ei[EE + e]], 1);   // dst row of edge_index
}

__global__ void k_dinv() {
    int i = blockIdx.x * blockDim.x + threadIdx.x;
    if (i < NN) g_dinv[i] = rsqrtf((float)(g_deg[i] + 1));  // +1 self-loop
}

__global__ void k_scan_local() {
    __shared__ int sh[SCAN_B];
    int tx = threadIdx.x;
    int i = blockIdx.x * SCAN_B + tx;
    int v = (i < NN) ? g_deg[i] : 0;
    sh[tx] = v;
    __syncthreads();
    for (int off = 1; off < SCAN_B; off <<= 1) {
        int t = (tx >= off) ? sh[tx - off] : 0;
        __syncthreads();
        sh[tx] += t;
        __syncthreads();
    }
    if (i < NN) g_rowptr[i] = sh[tx] - v;        // exclusive
    if (tx == SCAN_B - 1) g_part[blockIdx.x] = sh[tx];
}

__global__ void k_scan_part() {
    __shared__ int sh[128];
    int tx = threadIdx.x;
    int v = (tx < NB) ? g_part[tx] : 0;
    sh[tx] = v;
    __syncthreads();
    for (int off = 1; off < 128; off <<= 1) {
        int t = (tx >= off) ? sh[tx - off] : 0;
        __syncthreads();
        sh[tx] += t;
        __syncthreads();
    }
    if (tx < NB) g_part[tx] = sh[tx] - v;        // exclusive block offsets
}

__global__ void k_scan_add() {
    int i = blockIdx.x * blockDim.x + threadIdx.x;
    if (i < NN) {
        int v = g_rowptr[i] + g_part[i >> 10];
        g_rowptr[i] = v;
        g_cursor[i] = v;
    }
    if (i == 0) g_rowptr[NN] = EE;
}

__global__ void k_fill(const int* __restrict__ ei) {
    int e = blockIdx.x * blockDim.x + threadIdx.x;
    if (e < EE) {
        int src = ei[e];
        int dst = ei[EE + e];
        int p = atomicAdd(&g_cursor[dst], 1);
        g_col[p] = src;
    }
}

__global__ void k_gcnt(const int* __restrict__ batch) {
    int i = blockIdx.x * blockDim.x + threadIdx.x;
    if (i < NN) atomicAdd(&g_gcnt[batch[i]], 1);
}

// ---------------- GEMM: Y[N,128] = X[N,128] @ W[128,128] -------------------
// Block computes 128 rows x 128 cols. 256 threads, 8x8 per thread.
__global__ void __launch_bounds__(256) k_gemm(const float* __restrict__ X,
                                              const float* __restrict__ W,
                                              float* __restrict__ Y) {
    extern __shared__ float sh[];
    float* Xs = sh;            // 128 x 128
    float* Ws = sh + 128 * 128;

    int tid = threadIdx.x;
    int row0 = blockIdx.x * 128;

    const float4* X4 = (const float4*)X;
    const float4* W4 = (const float4*)W;
#pragma unroll
    for (int i = 0; i < 16; i++) {
        int idx = i * 256 + tid;          // 4096 float4 per tile
        int r = idx >> 5, c = idx & 31;
        float4 v = make_float4(0.f, 0.f, 0.f, 0.f);
        if (row0 + r < NN) v = X4[(size_t)(row0 + r) * 32 + c];
        ((float4*)Xs)[idx] = v;
        ((float4*)Ws)[idx] = W4[idx];
    }
    __syncthreads();

    int tx = tid & 15;      // col group (x8)
    int ty = tid >> 4;      // row group (x8)
    int cb = tx * 8;
    int rb = ty * 8;

    float acc[8][8];
#pragma unroll
    for (int r = 0; r < 8; r++)
#pragma unroll
        for (int c = 0; c < 8; c++) acc[r][c] = 0.f;

#pragma unroll 4
    for (int k = 0; k < 128; k++) {
        float a[8], b[8];
        const float4* wrow = (const float4*)(Ws + k * 128 + cb);
        float4 b0 = wrow[0];
        float4 b1 = wrow[1];
        b[0] = b0.x; b[1] = b0.y; b[2] = b0.z; b[3] = b0.w;
        b[4] = b1.x; b[5] = b1.y; b[6] = b1.z; b[7] = b1.w;
#pragma unroll
        for (int r = 0; r < 8; r++) a[r] = Xs[(rb + r) * 128 + k];
#pragma unroll
        for (int r = 0; r < 8; r++)
#pragma unroll
            for (int c = 0; c < 8; c++)
                acc[r][c] = fmaf(a[r], b[c], acc[r][c]);
    }

#pragma unroll
    for (int r = 0; r < 8; r++) {
        int row = row0 + rb + r;
        if (row < NN) {
            float4* o = (float4*)(Y + (size_t)row * 128 + cb);
            o[0] = make_float4(acc[r][0], acc[r][1], acc[r][2], acc[r][3]);
            o[1] = make_float4(acc[r][4], acc[r][5], acc[r][6], acc[r][7]);
        }
    }
}

// ---------------- aggregation + BN + ReLU (one warp per node) --------------
// reads g_buf0 (t = XW), writes g_buf1 (unless FINAL: reduces to g_gsum)
template <bool FINAL>
__global__ void __launch_bounds__(256) k_agg(const float* __restrict__ bias,
                                             const float* __restrict__ gamma,
                                             const float* __restrict__ beta,
                                             const float* __restrict__ mean,
                                             const float* __restrict__ var,
                                             const float* __restrict__ Wl,
                                             const int* __restrict__ batch) {
    int warp = (blockIdx.x * blockDim.x + threadIdx.x) >> 5;
    int lane = threadIdx.x & 31;
    if (warp >= NN) return;
    int i = warp;

    const float4* T4 = (const float4*)g_buf0;
    float di = g_dinv[i];

    // self-loop term
    float4 acc = T4[(size_t)i * 32 + lane];
    float ws = di * di;
    acc.x *= ws; acc.y *= ws; acc.z *= ws; acc.w *= ws;

    int e0 = g_rowptr[i];
    int e1 = g_rowptr[i + 1];
    for (int e = e0; e < e1; ++e) {
        int s = __ldg(&g_col[e]);
        float w = di * __ldg(&g_dinv[s]);
        float4 v = T4[(size_t)s * 32 + lane];
        acc.x = fmaf(w, v.x, acc.x);
        acc.y = fmaf(w, v.y, acc.y);
        acc.z = fmaf(w, v.z, acc.z);
        acc.w = fmaf(w, v.w, acc.w);
    }

    float4 b  = ((const float4*)bias)[lane];
    float4 ga = ((const float4*)gamma)[lane];
    float4 be = ((const float4*)beta)[lane];
    float4 m  = ((const float4*)mean)[lane];
    float4 v_ = ((const float4*)var)[lane];

    float4 y;
    y.x = fmaxf(0.f, (acc.x + b.x - m.x) * rsqrtf(v_.x + BN_EPS) * ga.x + be.x);
    y.y = fmaxf(0.f, (acc.y + b.y - m.y) * rsqrtf(v_.y + BN_EPS) * ga.y + be.y);
    y.z = fmaxf(0.f, (acc.z + b.z - m.z) * rsqrtf(v_.z + BN_EPS) * ga.z + be.z);
    y.w = fmaxf(0.f, (acc.w + b.w - m.w) * rsqrtf(v_.w + BN_EPS) * ga.w + be.w);

    if (!FINAL) {
        ((float4*)g_buf1)[(size_t)i * 32 + lane] = y;
    } else {
        float4 wl = ((const float4*)Wl)[lane];
        float s = y.x * wl.x + y.y * wl.y + y.z * wl.z + y.w * wl.w;
#pragma unroll
        for (int off = 16; off > 0; off >>= 1)
            s += __shfl_xor_sync(0xFFFFFFFFu, s, off);
        if (lane == 0) atomicAdd(&g_gsum[batch[i]], s);
    }
}

__global__ void k_final(float* __restrict__ out, const float* __restrict__ bl) {
    int g = blockIdx.x * blockDim.x + threadIdx.x;
    if (g < GG) out[g] = g_gsum[g] / fmaxf((float)g_gcnt[g], 1.0f) + bl[0];
}

// ---------------- host launcher --------------------------------------------
extern "C" void kernel_launch(void* const* d_in, const int* in_sizes, int n_in,
                              void* d_out, int out_size) {
    const float* x     = (const float*)d_in[0];
    const int*   ei    = (const int*)d_in[1];
    const int*   batch = (const int*)d_in[2];
    const float* W1 = (const float*)d_in[3];
    const float* b1 = (const float*)d_in[4];
    const float* g1 = (const float*)d_in[5];
    const float* be1 = (const float*)d_in[6];
    const float* m1 = (const float*)d_in[7];
    const float* v1 = (const float*)d_in[8];
    const float* W2 = (const float*)d_in[9];
    const float* b2 = (const float*)d_in[10];
    const float* g2 = (const float*)d_in[11];
    const float* be2 = (const float*)d_in[12];
    const float* m2 = (const float*)d_in[13];
    const float* v2 = (const float*)d_in[14];
    const float* W3 = (const float*)d_in[15];
    const float* b3 = (const float*)d_in[16];
    const float* g3 = (const float*)d_in[17];
    const float* be3 = (const float*)d_in[18];
    const float* m3 = (const float*)d_in[19];
    const float* v3 = (const float*)d_in[20];
    const float* Wl = (const float*)d_in[21];
    const float* bl = (const float*)d_in[22];

    float *buf0, *buf1;
    cudaGetSymbolAddress((void**)&buf0, g_buf0);
    cudaGetSymbolAddress((void**)&buf1, g_buf1);

    cudaFuncSetAttribute(k_gemm, cudaFuncAttributeMaxDynamicSharedMemorySize,
                         2 * 128 * 128 * (int)sizeof(float));

    const int TPB = 256;
    // ---- graph preprocessing (CSR by dst, dinv, per-graph counts)
    k_zero<<<(NN + TPB - 1) / TPB, TPB>>>();
    k_hist<<<(EE + TPB - 1) / TPB, TPB>>>(ei);
    k_dinv<<<(NN + TPB - 1) / TPB, TPB>>>();
    k_scan_local<<<NB, SCAN_B>>>();
    k_scan_part<<<1, 128>>>();
    k_scan_add<<<(NN + TPB) / TPB, TPB>>>();
    k_fill<<<(EE + TPB - 1) / TPB, TPB>>>(ei);
    k_gcnt<<<(NN + TPB - 1) / TPB, TPB>>>(batch);

    const int GEMM_BLOCKS = (NN + 127) / 128;           // 782
    const int GEMM_SMEM = 2 * 128 * 128 * (int)sizeof(float);
    const int AGG_BLOCKS = (NN * 32 + TPB - 1) / TPB;   // 12500

    // ---- layer 1
    k_gemm<<<GEMM_BLOCKS, 256, GEMM_SMEM>>>(x, W1, buf0);
    k_agg<false><<<AGG_BLOCKS, TPB>>>(b1, g1, be1, m1, v1, nullptr, nullptr);
    // ---- layer 2
    k_gemm<<<GEMM_BLOCKS, 256, GEMM_SMEM>>>(buf1, W2, buf0);
    k_agg<false><<<AGG_BLOCKS, TPB>>>(b2, g2, be2, m2, v2, nullptr, nullptr);
    // ---- layer 3 (fused mean-pool + linear head via per-node dot)
    k_gemm<<<GEMM_BLOCKS, 256, GEMM_SMEM>>>(buf1, W3, buf0);
    k_agg<true><<<AGG_BLOCKS, TPB>>>(b3, g3, be3, m3, v3, Wl, batch);

    k_final<<<(GG + TPB - 1) / TPB, TPB>>>((float*)d_out, bl);
}

// round 3
// speedup vs baseline: 1.7873x; 1.7873x over previous
#include <cuda_runtime.h>
#include <cuda_fp16.h>
#include <cstdint>

#define NN 100000
#define EE 1600000
#define HH 128
#define GG 512
#define BN_EPS 1e-5f
#define SCAN_B 1024
#define NB ((NN + SCAN_B - 1) / SCAN_B)   // 98 scan blocks

// ---------------- scratch (device globals: no allocation allowed) -----------
__device__ __half g_t[(size_t)NN * HH];   // GEMM output t = h @ W' (fp16)
__device__ __half g_h[(size_t)NN * HH];   // activated hidden (fp16)
__device__ __half g_Wh[3 * HH * HH];      // BN-folded fp16 weights
__device__ float  g_beta[3 * HH];         // BN-folded shifts
__device__ float  g_dinv[NN];
__device__ int    g_deg[NN];
__device__ int    g_rowptr[NN + 1];
__device__ int    g_cursor[NN];
__device__ int    g_col[EE];
__device__ float  g_gsum[GG];
__device__ int    g_gcnt[GG];
__device__ int    g_part[NB];

__device__ __forceinline__ uint32_t s2u(const void* p) {
    return (uint32_t)__cvta_generic_to_shared(p);
}

// ---------------- preprocessing kernels ------------------------------------
__global__ void k_zero() {
    int i = blockIdx.x * blockDim.x + threadIdx.x;
    if (i < NN) g_deg[i] = 0;
    if (i < GG) { g_gsum[i] = 0.0f; g_gcnt[i] = 0; }
}

__global__ void k_hist(const int* __restrict__ ei) {
    int e = blockIdx.x * blockDim.x + threadIdx.x;
    if (e < EE) atomicAdd(&g_deg[ei[EE + e]], 1);   // dst row of edge_index
}

__global__ void k_dinv() {
    int i = blockIdx.x * blockDim.x + threadIdx.x;
    if (i < NN) g_dinv[i] = rsqrtf((float)(g_deg[i] + 1));  // +1 self-loop
}

__global__ void k_scan_local() {
    __shared__ int sh[SCAN_B];
    int tx = threadIdx.x;
    int i = blockIdx.x * SCAN_B + tx;
    int v = (i < NN) ? g_deg[i] : 0;
    sh[tx] = v;
    __syncthreads();
    for (int off = 1; off < SCAN_B; off <<= 1) {
        int t = (tx >= off) ? sh[tx - off] : 0;
        __syncthreads();
        sh[tx] += t;
        __syncthreads();
    }
    if (i < NN) g_rowptr[i] = sh[tx] - v;        // exclusive
    if (tx == SCAN_B - 1) g_part[blockIdx.x] = sh[tx];
}

__global__ void k_scan_part() {
    __shared__ int sh[128];
    int tx = threadIdx.x;
    int v = (tx < NB) ? g_part[tx] : 0;
    sh[tx] = v;
    __syncthreads();
    for (int off = 1; off < 128; off <<= 1) {
        int t = (tx >= off) ? sh[tx - off] : 0;
        __syncthreads();
        sh[tx] += t;
        __syncthreads();
    }
    if (tx < NB) g_part[tx] = sh[tx] - v;        // exclusive block offsets
}

__global__ void k_scan_add() {
    int i = blockIdx.x * blockDim.x + threadIdx.x;
    if (i < NN) {
        int v = g_rowptr[i] + g_part[i >> 10];
        g_rowptr[i] = v;
        g_cursor[i] = v;
    }
    if (i == 0) g_rowptr[NN] = EE;
}

__global__ void k_fill(const int* __restrict__ ei) {
    int e = blockIdx.x * blockDim.x + threadIdx.x;
    if (e < EE) {
        int src = ei[e];
        int dst = ei[EE + e];
        int p = atomicAdd(&g_cursor[dst], 1);
        g_col[p] = src;
    }
}

__global__ void k_gcnt(const int* __restrict__ batch) {
    int i = blockIdx.x * blockDim.x + threadIdx.x;
    if (i < NN) atomicAdd(&g_gcnt[batch[i]], 1);
}

// Fold BN scale into W columns (fp16), compute folded shift beta.
__global__ void k_prep_w(const float* __restrict__ W, const float* __restrict__ b,
                         const float* __restrict__ ga, const float* __restrict__ be,
                         const float* __restrict__ m, const float* __restrict__ v,
                         int layer) {
    int idx = blockIdx.x * blockDim.x + threadIdx.x;
    if (idx < HH * HH) {
        int n = idx & (HH - 1);
        float alpha = ga[n] * rsqrtf(v[n] + BN_EPS);
        g_Wh[layer * HH * HH + idx] = __float2half(W[idx] * alpha);
    }
    if (idx < HH) {
        float alpha = ga[idx] * rsqrtf(v[idx] + BN_EPS);
        g_beta[layer * HH + idx] = (b[idx] - m[idx]) * alpha + be[idx];
    }
}

// ---------------- fp16 tensor-core GEMM: Y[N,128] = X[N,128] @ W[128,128] ---
// 128x128 tile / block, 8 warps, each warp m16 x n128, mma.m16n8k16 fp16.
// Smem rows padded to 136 halves (272 B) -> ldmatrix bank-conflict-free.
template <bool F32IN>
__global__ void __launch_bounds__(256) k_gemm_tc(const void* __restrict__ Xv,
                                                 const __half* __restrict__ W,
                                                 __half* __restrict__ Y) {
    extern __shared__ __half sh[];
    __half* As = sh;               // 128 x 136
    __half* Ws = sh + 128 * 136;   // 128 x 136 (row = k, cols = n)

    int tid = threadIdx.x;
    int row0 = blockIdx.x * 128;

    // load W tile (fp16, 128x128)
    const uint4* Wg = (const uint4*)W;
#pragma unroll
    for (int i = 0; i < 8; i++) {
        int idx = i * 256 + tid;          // uint4 = 8 halves; 2048 total
        int r = idx >> 4, c = (idx & 15) * 8;
        *(uint4*)&Ws[r * 136 + c] = Wg[idx];
    }
    // load A tile
    if (F32IN) {
        const float4* Xg = (const float4*)Xv;
#pragma unroll
        for (int i = 0; i < 16; i++) {
            int idx = i * 256 + tid;      // float4; 4096 total
            int r = idx >> 5, c = (idx & 31) * 4;
            float4 v = make_float4(0.f, 0.f, 0.f, 0.f);
            if (row0 + r < NN) v = Xg[(size_t)(row0 + r) * 32 + (idx & 31)];
            *(__half2*)&As[r * 136 + c]     = __floats2half2_rn(v.x, v.y);
            *(__half2*)&As[r * 136 + c + 2] = __floats2half2_rn(v.z, v.w);
        }
    } else {
        const uint4* Xg = (const uint4*)Xv;
#pragma unroll
        for (int i = 0; i < 8; i++) {
            int idx = i * 256 + tid;      // uint4 = 8 halves; 2048 total
            int r = idx >> 4, c = (idx & 15) * 8;
            uint4 v = make_uint4(0, 0, 0, 0);
            if (row0 + r < NN) v = Xg[(size_t)(row0 + r) * 16 + (idx & 15)];
            *(uint4*)&As[r * 136 + c] = v;
        }
    }
    __syncthreads();

    int wid = tid >> 5, lane = tid & 31;
    int m0 = wid * 16;

    float acc[16][4];
#pragma unroll
    for (int nt = 0; nt < 16; nt++)
#pragma unroll
        for (int c = 0; c < 4; c++) acc[nt][c] = 0.f;

#pragma unroll
    for (int ks = 0; ks < 8; ks++) {
        uint32_t a0, a1, a2, a3;
        uint32_t aaddr = s2u(&As[(m0 + (lane & 15)) * 136 + ks * 16 + (lane >> 4) * 8]);
        asm volatile("ldmatrix.sync.aligned.m8n8.x4.shared.b16 {%0,%1,%2,%3}, [%4];"
                     : "=r"(a0), "=r"(a1), "=r"(a2), "=r"(a3) : "r"(aaddr));
        uint32_t brow = s2u(&Ws[(ks * 16 + (lane & 15)) * 136]);
#pragma unroll
        for (int nt = 0; nt < 16; nt++) {
            uint32_t b0, b1;
            uint32_t baddr = brow + nt * 8 * 2;
            asm volatile("ldmatrix.sync.aligned.m8n8.x2.trans.shared.b16 {%0,%1}, [%2];"
                         : "=r"(b0), "=r"(b1) : "r"(baddr));
            asm volatile(
                "mma.sync.aligned.m16n8k16.row.col.f32.f16.f16.f32 "
                "{%0,%1,%2,%3}, {%4,%5,%6,%7}, {%8,%9}, {%0,%1,%2,%3};"
                : "+f"(acc[nt][0]), "+f"(acc[nt][1]), "+f"(acc[nt][2]), "+f"(acc[nt][3])
                : "r"(a0), "r"(a1), "r"(a2), "r"(a3), "r"(b0), "r"(b1));
        }
    }

    int r0 = row0 + m0 + (lane >> 2);
    int cb = (lane & 3) * 2;
#pragma unroll
    for (int nt = 0; nt < 16; nt++) {
        if (r0 < NN)
            *(__half2*)&Y[(size_t)r0 * 128 + nt * 8 + cb] =
                __floats2half2_rn(acc[nt][0], acc[nt][1]);
        if (r0 + 8 < NN)
            *(__half2*)&Y[(size_t)(r0 + 8) * 128 + nt * 8 + cb] =
                __floats2half2_rn(acc[nt][2], acc[nt][3]);
    }
}

// ---------------- aggregation + folded-BN + ReLU (one warp per node) -------
// reads g_t (fp16), writes g_h (fp16) unless FINAL (reduce -> g_gsum)
template <bool FINAL>
__global__ void __launch_bounds__(256) k_agg16(const float* __restrict__ beta,
                                               const float* __restrict__ Wl,
                                               const int* __restrict__ batch) {
    int warp = (blockIdx.x * blockDim.x + threadIdx.x) >> 5;
    int lane = threadIdx.x & 31;
    if (warp >= NN) return;
    int i = warp;

    const uint2* T = (const uint2*)g_t;   // 32 x uint2 (4 halves) per row
    float di = g_dinv[i];

    uint2 u = T[(size_t)i * 32 + lane];
    __half2 p0 = *(__half2*)&u.x, p1 = *(__half2*)&u.y;
    float2 f0 = __half22float2(p0), f1 = __half22float2(p1);
    float ws = di * di;
    float4 acc = make_float4(f0.x * ws, f0.y * ws, f1.x * ws, f1.y * ws);

    int e0 = g_rowptr[i];
    int e1 = g_rowptr[i + 1];
    for (int e = e0; e < e1; ++e) {
        int s = __ldg(&g_col[e]);
        float w = di * __ldg(&g_dinv[s]);
        uint2 v = T[(size_t)s * 32 + lane];
        float2 a = __half22float2(*(__half2*)&v.x);
        float2 b = __half22float2(*(__half2*)&v.y);
        acc.x = fmaf(w, a.x, acc.x);
        acc.y = fmaf(w, a.y, acc.y);
        acc.z = fmaf(w, b.x, acc.z);
        acc.w = fmaf(w, b.y, acc.w);
    }

    float4 be = ((const float4*)beta)[lane];
    float4 y;
    y.x = fmaxf(0.f, acc.x + be.x);
    y.y = fmaxf(0.f, acc.y + be.y);
    y.z = fmaxf(0.f, acc.z + be.z);
    y.w = fmaxf(0.f, acc.w + be.w);

    if (!FINAL) {
        uint2 o;
        *(__half2*)&o.x = __floats2half2_rn(y.x, y.y);
        *(__half2*)&o.y = __floats2half2_rn(y.z, y.w);
        ((uint2*)g_h)[(size_t)i * 32 + lane] = o;
    } else {
        float4 wl = ((const float4*)Wl)[lane];
        float s = y.x * wl.x + y.y * wl.y + y.z * wl.z + y.w * wl.w;
#pragma unroll
        for (int off = 16; off > 0; off >>= 1)
            s += __shfl_xor_sync(0xFFFFFFFFu, s, off);
        if (lane == 0) atomicAdd(&g_gsum[batch[i]], s);
    }
}

__global__ void k_final(float* __restrict__ out, const float* __restrict__ bl) {
    int g = blockIdx.x * blockDim.x + threadIdx.x;
    if (g < GG) out[g] = g_gsum[g] / fmaxf((float)g_gcnt[g], 1.0f) + bl[0];
}

// ---------------- host launcher --------------------------------------------
extern "C" void kernel_launch(void* const* d_in, const int* in_sizes, int n_in,
                              void* d_out, int out_size) {
    const float* x     = (const float*)d_in[0];
    const int*   ei    = (const int*)d_in[1];
    const int*   batch = (const int*)d_in[2];
    const float* W1 = (const float*)d_in[3];
    const float* b1 = (const float*)d_in[4];
    const float* g1 = (const float*)d_in[5];
    const float* be1 = (const float*)d_in[6];
    const float* m1 = (const float*)d_in[7];
    const float* v1 = (const float*)d_in[8];
    const float* W2 = (const float*)d_in[9];
    const float* b2 = (const float*)d_in[10];
    const float* g2 = (const float*)d_in[11];
    const float* be2 = (const float*)d_in[12];
    const float* m2 = (const float*)d_in[13];
    const float* v2 = (const float*)d_in[14];
    const float* W3 = (const float*)d_in[15];
    const float* b3 = (const float*)d_in[16];
    const float* g3 = (const float*)d_in[17];
    const float* be3 = (const float*)d_in[18];
    const float* m3 = (const float*)d_in[19];
    const float* v3 = (const float*)d_in[20];
    const float* Wl = (const float*)d_in[21];
    const float* bl = (const float*)d_in[22];

    __half *t, *h, *Wh;
    float *beta;
    cudaGetSymbolAddress((void**)&t, g_t);
    cudaGetSymbolAddress((void**)&h, g_h);
    cudaGetSymbolAddress((void**)&Wh, g_Wh);
    cudaGetSymbolAddress((void**)&beta, g_beta);

    const int GEMM_SMEM = 2 * 128 * 136 * (int)sizeof(__half);   // 69632
    cudaFuncSetAttribute(k_gemm_tc<true>,  cudaFuncAttributeMaxDynamicSharedMemorySize, GEMM_SMEM);
    cudaFuncSetAttribute(k_gemm_tc<false>, cudaFuncAttributeMaxDynamicSharedMemorySize, GEMM_SMEM);

    const int TPB = 256;
    // ---- graph preprocessing (CSR by dst, dinv, per-graph counts)
    k_zero<<<(NN + TPB - 1) / TPB, TPB>>>();
    k_hist<<<(EE + TPB - 1) / TPB, TPB>>>(ei);
    k_dinv<<<(NN + TPB - 1) / TPB, TPB>>>();
    k_scan_local<<<NB, SCAN_B>>>();
    k_scan_part<<<1, 128>>>();
    k_scan_add<<<(NN + TPB) / TPB, TPB>>>();
    k_fill<<<(EE + TPB - 1) / TPB, TPB>>>(ei);
    k_gcnt<<<(NN + TPB - 1) / TPB, TPB>>>(batch);

    // ---- weight prep: fold BN scale into W, convert to fp16
    k_prep_w<<<64, 256>>>(W1, b1, g1, be1, m1, v1, 0);
    k_prep_w<<<64, 256>>>(W2, b2, g2, be2, m2, v2, 1);
    k_prep_w<<<64, 256>>>(W3, b3, g3, be3, m3, v3, 2);

    const int GEMM_BLOCKS = (NN + 127) / 128;           // 782
    const int AGG_BLOCKS = (NN * 32 + TPB - 1) / TPB;   // 12500

    // ---- layer 1
    k_gemm_tc<true><<<GEMM_BLOCKS, 256, GEMM_SMEM>>>(x, Wh, t);
    k_agg16<false><<<AGG_BLOCKS, TPB>>>(beta, nullptr, nullptr);
    // ---- layer 2
    k_gemm_tc<false><<<GEMM_BLOCKS, 256, GEMM_SMEM>>>(h, Wh + HH * HH, t);
    k_agg16<false><<<AGG_BLOCKS, TPB>>>(beta + HH, nullptr, nullptr);
    // ---- layer 3 (fused mean-pool + linear head via per-node dot)
    k_gemm_tc<false><<<GEMM_BLOCKS, 256, GEMM_SMEM>>>(h, Wh + 2 * HH * HH, t);
    k_agg16<true><<<AGG_BLOCKS, TPB>>>(beta + 2 * HH, Wl, batch);

    k_final<<<(GG + TPB - 1) / TPB, TPB>>>((float*)d_out, bl);
}